// round 13
// baseline (speedup 1.0000x reference)
#include <cuda_runtime.h>
#include <math.h>

// Problem constants (fixed for this instance)
#define Bb 2
#define Nn 16384
#define Mm 16384
#define Ee 49152

typedef unsigned long long ull;

// ---------------- scratch (no allocations allowed) ----------------
__device__ float4   g_predP[Bb * Nn];   // (x, y, z, 0.5*|p|^2)
__device__ float4   g_tgtP [Bb * Mm];   // (x, y, z, 0.5*|t|^2)
__device__ unsigned g_rowmin[Bb * Nn];  // monotone-key encoded min over m of d2/2
__device__ unsigned g_colmin[Bb * Mm];  // monotone-key encoded min over n of d2/2
__device__ double   g_es1[Bb];          // sum of edge lengths per batch
__device__ double   g_es2[Bb];          // sum of squared edge lengths per batch
__device__ double   g_sumRow;           // sum over all (b,n) of min-dist
__device__ double   g_sumCol;           // sum over all (b,m) of min-dist
__device__ int      g_edges_is64;       // runtime-detected edges dtype

// Monotone float<->uint key: atomicMin on key == min on float (handles negatives).
__device__ __forceinline__ unsigned f2o(float f) {
    unsigned b = __float_as_uint(f);
    return (b & 0x80000000u) ? ~b : (b ^ 0x80000000u);
}
__device__ __forceinline__ float o2f(unsigned k) {
    return __uint_as_float((k & 0x80000000u) ? (k ^ 0x80000000u) : ~k);
}

// ---------------- packed f32x2 helpers (Blackwell; PTX-only forms) ----------------
__device__ __forceinline__ ull pack2(float lo, float hi) {
    ull r; asm("mov.b64 %0, {%1, %2};" : "=l"(r) : "f"(lo), "f"(hi)); return r;
}
__device__ __forceinline__ void unpack2(ull v, float& lo, float& hi) {
    asm("mov.b64 {%0, %1}, %2;" : "=f"(lo), "=f"(hi) : "l"(v));
}
__device__ __forceinline__ ull fma2(ull a, ull b, ull c) {
    ull d; asm("fma.rn.f32x2 %0, %1, %2, %3;" : "=l"(d) : "l"(a), "l"(b), "l"(c)); return d;
}
__device__ __forceinline__ ull add2(ull a, ull b) {
    ull d; asm("add.rn.f32x2 %0, %1, %2;" : "=l"(d) : "l"(a), "l"(b)); return d;
}

// ---------------- prep: pack points, reset scratch, classify edges dtype ----------------
// int64 edges: values < 16384 -> every odd 32-bit word (high half) is 0.
// int32 edges: odd words uniform in [0,16384); 8 zeros has prob ~2^-112.
__global__ void prep_kernel(const float* __restrict__ pred, const float* __restrict__ tgt,
                            const int* __restrict__ e32) {
    int i = blockIdx.x * blockDim.x + threadIdx.x;  // 0 .. Bb*Nn-1 (Nn == Mm)
    if (i < Bb * Nn) {
        float x = pred[3 * i], y = pred[3 * i + 1], z = pred[3 * i + 2];
        g_predP[i] = make_float4(x, y, z, 0.5f * (x * x + y * y + z * z));
        g_rowmin[i] = 0xFFFFFFFFu;
        float tx = tgt[3 * i], ty = tgt[3 * i + 1], tz = tgt[3 * i + 2];
        g_tgtP[i] = make_float4(tx, ty, tz, 0.5f * (tx * tx + ty * ty + tz * tz));
        g_colmin[i] = 0xFFFFFFFFu;
    }
    if (i < Bb) { g_es1[i] = 0.0; g_es2[i] = 0.0; }
    if (i == 0) {
        g_sumRow = 0.0; g_sumCol = 0.0;
        int is64 = 1;
#pragma unroll
        for (int k = 0; k < 8; k++)
            if (e32[2 * k + 1] != 0) is64 = 0;
        g_edges_is64 = is64;
    }
}

// ---------------- pairwise min kernel (row-packed f32x2) ----------------
// Grid: (8 col-tiles, 128 row-blocks, Bb). Block: 16x16 = 256 threads.
// Block covers 128 rows x 2048 cols (16 iterations of 128 cols).
// Thread patch per iter: 8 rows (as 4 f32x2 ROW-pairs) x 8 cols.
// P packed over row-pairs (no duplicated halves -> 32 regs, occ 3 blocks/SM).
// T staged duplicated in smem: sXY[c]=((x,x),(y,y)), sZW[c]=((z,z),(w,w));
// stride-16B access across tx -> conflict-free, ty-halves broadcast-dedup.
// Per 2 pairs (2 rows, 1 col): 1 ADD2 + 3 FMA2 (fma pipe) + 4 FMNMX (alu).
#define COLS_PER_BLOCK 2048
#define COL_ITERS 16

__global__ __launch_bounds__(256, 3) void pair_kernel() {
    __shared__ ulonglong2 sXY[128];   // per col: (x,x | y,y)
    __shared__ ulonglong2 sZW[128];   // per col: (z,z | w,w)  w = 0.5|t|^2
    __shared__ float      scp[8][132]; // col partials after warp pre-fold

    const int tx = threadIdx.x, ty = threadIdx.y;
    const int tid = ty * 16 + tx;
    const int b = blockIdx.z;
    const int rowBase = blockIdx.y * 128;
    const int colBase = blockIdx.x * COLS_PER_BLOCK;

    // Load this thread's 8 pred rows; pack per ROW-PAIR (negated xyz).
    const float4* pp = g_predP + b * Nn + rowBase + ty * 8;
    ull Px2[4], Py2[4], Pz2[4], Pw2[4];
#pragma unroll
    for (int rp = 0; rp < 4; rp++) {
        float4 A = pp[2 * rp], Bv = pp[2 * rp + 1];
        Px2[rp] = pack2(-A.x, -Bv.x);
        Py2[rp] = pack2(-A.y, -Bv.y);
        Pz2[rp] = pack2(-A.z, -Bv.z);
        Pw2[rp] = pack2( A.w,  Bv.w);
    }

    float rA[8];
#pragma unroll
    for (int i = 0; i < 8; i++) rA[i] = 3.4e38f;

    const float4* tp = g_tgtP + b * Mm + colBase;

    for (int it = 0; it < COL_ITERS; ++it) {
        __syncthreads();                       // protect sXY/sZW/scp reuse
        if (tid < 128) {
            float4 T = tp[it * 128 + tid];
            sXY[tid] = make_ulonglong2(pack2(T.x, T.x), pack2(T.y, T.y));
            sZW[tid] = make_ulonglong2(pack2(T.z, T.z), pack2(T.w, T.w));
        }
        __syncthreads();

#pragma unroll
        for (int cm = 0; cm < 8; cm++) {
            const ulonglong2 xy = sXY[cm * 16 + tx];
            const ulonglong2 zw = sZW[cm * 16 + tx];
            float cmin = 3.4e38f;
#pragma unroll
            for (int rp = 0; rp < 4; rp++) {
                ull acc = add2(zw.y, Pw2[rp]);
                acc = fma2(Pz2[rp], zw.x, acc);
                acc = fma2(Py2[rp], xy.y, acc);
                acc = fma2(Px2[rp], xy.x, acc);
                float lo, hi; unpack2(acc, lo, hi);  // lo=row 2rp, hi=row 2rp+1
                rA[2 * rp]     = fminf(rA[2 * rp], lo);
                rA[2 * rp + 1] = fminf(rA[2 * rp + 1], hi);
                cmin = fminf(cmin, fminf(lo, hi));
            }
            // warp pre-fold: lanes (tx,ty) and (tx,ty^1) share a warp (xor 16)
            cmin = fminf(cmin, __shfl_xor_sync(0xffffffffu, cmin, 16));
            if ((ty & 1) == 0) scp[ty >> 1][cm * 16 + tx] = cmin;
        }
        __syncthreads();
        if (tid < 128) {
            float m = scp[0][tid];
#pragma unroll
            for (int k = 1; k < 8; k++) m = fminf(m, scp[k][tid]);
            atomicMin(&g_colmin[b * Mm + colBase + it * 128 + tid], f2o(m));
        }
    }

    // Row mins: reduce across the 16 tx lanes (xor 1,2,4,8 stays within ty half)
#pragma unroll
    for (int o = 1; o < 16; o <<= 1) {
#pragma unroll
        for (int rn = 0; rn < 8; rn++)
            rA[rn] = fminf(rA[rn], __shfl_xor_sync(0xffffffffu, rA[rn], o));
    }
    if (tx == 0) {
#pragma unroll
        for (int rn = 0; rn < 8; rn++)
            atomicMin(&g_rowmin[b * Nn + rowBase + ty * 8 + rn], f2o(rA[rn]));
    }
}

// ---------------- edge loss partial sums ----------------
__global__ void edge_kernel(const float* __restrict__ pred, const void* __restrict__ edges) {
    const int b = blockIdx.y;
    const int is64 = g_edges_is64;
    const int*       E32 = (const int*)edges;
    const long long* E64 = (const long long*)edges;
    double s1 = 0.0, s2 = 0.0;
    for (int e = blockIdx.x * blockDim.x + threadIdx.x; e < Ee; e += gridDim.x * blockDim.x) {
        int a, c;
        if (is64) { a = (int)E64[2 * e]; c = (int)E64[2 * e + 1]; }
        else      { a = E32[2 * e];      c = E32[2 * e + 1]; }
        a &= (Nn - 1); c &= (Nn - 1);   // defensive: never OOB even if dtype guess is wrong
        const float* v1 = pred + (size_t)(b * Nn + a) * 3;
        const float* v2 = pred + (size_t)(b * Nn + c) * 3;
        float dx = v1[0] - v2[0], dy = v1[1] - v2[1], dz = v1[2] - v2[2];
        float l = sqrtf(fmaf(dx, dx, fmaf(dy, dy, dz * dz)));
        s1 += (double)l;
        s2 += (double)l * (double)l;
    }
    // warp then block reduce
    for (int o = 16; o > 0; o >>= 1) {
        s1 += __shfl_down_sync(0xffffffffu, s1, o);
        s2 += __shfl_down_sync(0xffffffffu, s2, o);
    }
    __shared__ double sh1[8], sh2[8];
    int lane = threadIdx.x & 31, w = threadIdx.x >> 5;
    if (lane == 0) { sh1[w] = s1; sh2[w] = s2; }
    __syncthreads();
    if (threadIdx.x == 0) {
        double a1 = 0.0, a2 = 0.0;
        for (int k = 0; k < (int)blockDim.x / 32; k++) { a1 += sh1[k]; a2 += sh2[k]; }
        atomicAdd(&g_es1[b], a1);
        atomicAdd(&g_es2[b], a2);
    }
}

// ---------------- grid-wide min-array reduction ----------------
__global__ void reduce_kernel() {
    const int tid = blockIdx.x * blockDim.x + threadIdx.x;
    const int stride = gridDim.x * blockDim.x;
    double sRow = 0.0, sCol = 0.0;
    for (int i = tid; i < Bb * Nn; i += stride) {
        float vr = o2f(g_rowmin[i]);
        float vc = o2f(g_colmin[i]);
        sRow += (double)sqrtf(fmaxf(2.0f * vr, 0.0f));
        sCol += (double)sqrtf(fmaxf(2.0f * vc, 0.0f));
    }
    for (int o = 16; o > 0; o >>= 1) {
        sRow += __shfl_down_sync(0xffffffffu, sRow, o);
        sCol += __shfl_down_sync(0xffffffffu, sCol, o);
    }
    __shared__ double shA[8], shB[8];
    int lane = threadIdx.x & 31, w = threadIdx.x >> 5;
    if (lane == 0) { shA[w] = sRow; shB[w] = sCol; }
    __syncthreads();
    if (threadIdx.x == 0) {
        double a = 0.0, c = 0.0;
#pragma unroll
        for (int k = 0; k < 8; k++) { a += shA[k]; c += shB[k]; }
        atomicAdd(&g_sumRow, a);
        atomicAdd(&g_sumCol, c);
    }
}

// ---------------- final scalar combine ----------------
__global__ void final_kernel(float* __restrict__ out) {
    if (threadIdx.x != 0) return;
    double c_loss = g_sumRow / (double)(Bb * Nn) + g_sumCol / (double)(Bb * Mm);
    double el = 0.0;
    for (int bb = 0; bb < Bb; bb++) {
        double mean = g_es1[bb] / (double)Ee;
        double var = (g_es2[bb] - (double)Ee * mean * mean) / (double)(Ee - 1);
        el += var;
    }
    el /= (double)Bb;
    double total = 1.0 * c_loss + 0.1 * el;
    out[0] = (float)total;
    out[1] = (float)c_loss;
    out[2] = (float)el;
}

// ---------------- launch ----------------
extern "C" void kernel_launch(void* const* d_in, const int* in_sizes, int n_in,
                              void* d_out, int out_size) {
    const float* pred  = (const float*)d_in[0];   // (B,N,3) f32
    const float* tgt   = (const float*)d_in[1];   // (B,M,3) f32
    const void*  edges = d_in[2];                 // (E,2) int32 (JAX x64 off) or int64
    (void)in_sizes; (void)n_in; (void)out_size;

    prep_kernel<<<(Bb * Nn + 255) / 256, 256>>>(pred, tgt, (const int*)edges);
    pair_kernel<<<dim3(Mm / COLS_PER_BLOCK, Nn / 128, Bb), dim3(16, 16)>>>();
    edge_kernel<<<dim3(192, Bb), 256>>>(pred, edges);
    reduce_kernel<<<128, 256>>>();
    final_kernel<<<1, 32>>>((float*)d_out);
}

// round 15
// speedup vs baseline: 1.1557x; 1.1557x over previous
#include <cuda_runtime.h>
#include <math.h>

// Problem constants (fixed for this instance)
#define Bb 2
#define Nn 16384
#define Mm 16384
#define Ee 49152

typedef unsigned long long ull;

// ---------------- scratch (no allocations allowed) ----------------
__device__ float4   g_predP[Bb * Nn];   // (x, y, z, 0.5*|p|^2)
__device__ float4   g_tgtP [Bb * Mm];   // (x, y, z, 0.5*|t|^2)
__device__ unsigned g_rowmin[Bb * Nn];  // monotone-key encoded min over m of d2/2
__device__ unsigned g_colmin[Bb * Mm];  // monotone-key encoded min over n of d2/2
__device__ double   g_es1[Bb];          // sum of edge lengths per batch
__device__ double   g_es2[Bb];          // sum of squared edge lengths per batch
__device__ double   g_sumRow;           // sum over all (b,n) of min-dist
__device__ double   g_sumCol;           // sum over all (b,m) of min-dist
__device__ int      g_edges_is64;       // runtime-detected edges dtype

// Monotone float<->uint key: atomicMin on key == min on float (handles negatives).
__device__ __forceinline__ unsigned f2o(float f) {
    unsigned b = __float_as_uint(f);
    return (b & 0x80000000u) ? ~b : (b ^ 0x80000000u);
}
__device__ __forceinline__ float o2f(unsigned k) {
    return __uint_as_float((k & 0x80000000u) ? (k ^ 0x80000000u) : ~k);
}

// ---------------- packed f32x2 helpers (Blackwell; PTX-only forms) ----------------
__device__ __forceinline__ ull pack2(float lo, float hi) {
    ull r; asm("mov.b64 %0, {%1, %2};" : "=l"(r) : "f"(lo), "f"(hi)); return r;
}
__device__ __forceinline__ void unpack2(ull v, float& lo, float& hi) {
    asm("mov.b64 {%0, %1}, %2;" : "=f"(lo), "=f"(hi) : "l"(v));
}
__device__ __forceinline__ ull fma2(ull a, ull b, ull c) {
    ull d; asm("fma.rn.f32x2 %0, %1, %2, %3;" : "=l"(d) : "l"(a), "l"(b), "l"(c)); return d;
}
__device__ __forceinline__ ull add2(ull a, ull b) {
    ull d; asm("add.rn.f32x2 %0, %1, %2;" : "=l"(d) : "l"(a), "l"(b)); return d;
}

// ---------------- prep: pack points, reset scratch, classify edges dtype ----------------
// int64 edges: values < 16384 -> every odd 32-bit word (high half) is 0.
// int32 edges: odd words uniform in [0,16384); 8 zeros has prob ~2^-112.
__global__ void prep_kernel(const float* __restrict__ pred, const float* __restrict__ tgt,
                            const int* __restrict__ e32) {
    int i = blockIdx.x * blockDim.x + threadIdx.x;  // 0 .. Bb*Nn-1 (Nn == Mm)
    if (i < Bb * Nn) {
        float x = pred[3 * i], y = pred[3 * i + 1], z = pred[3 * i + 2];
        g_predP[i] = make_float4(x, y, z, 0.5f * (x * x + y * y + z * z));
        g_rowmin[i] = 0xFFFFFFFFu;
        float tx = tgt[3 * i], ty = tgt[3 * i + 1], tz = tgt[3 * i + 2];
        g_tgtP[i] = make_float4(tx, ty, tz, 0.5f * (tx * tx + ty * ty + tz * tz));
        g_colmin[i] = 0xFFFFFFFFu;
    }
    if (i < Bb) { g_es1[i] = 0.0; g_es2[i] = 0.0; }
    if (i == 0) {
        g_sumRow = 0.0; g_sumCol = 0.0;
        int is64 = 1;
#pragma unroll
        for (int k = 0; k < 8; k++)
            if (e32[2 * k + 1] != 0) is64 = 0;
        g_edges_is64 = is64;
    }
}

// ---------------- no-op spacer: positions pair_kernel as launch #4 for ncu ----------------
__global__ void noop_kernel() {}

// ---------------- pairwise min kernel (column-packed f32x2, double-buffered) ----------------
// Grid: (8 col-tiles, 128 row-blocks, Bb). Block: 16x16 = 256 threads.
// Block covers 128 rows x 2048 cols (16 iterations of 128 cols).
// Thread patch per iter: 8 rows x 8 cols as 4 f32x2 COL-pairs at pair idx cm*16+tx.
// T staged pair-SoA (16B/col, conflict-free); P duplicated in regs (reused 8x/col).
// Per 2 pairs: 1 ADD2 + 3 FMA2 (fma pipe) + 4 FMNMX (alu).
// Double-buffered sT and scp -> ONE __syncthreads per iteration.
#define COLS_PER_BLOCK 2048
#define COL_ITERS 16

__global__ __launch_bounds__(256, 2) void pair_kernel() {
    __shared__ ulonglong2 sTxy[2][64];   // per col-pair: (x0,x1 | y0,y1)
    __shared__ ulonglong2 sTzw[2][64];   // per col-pair: (z0,z1 | w0,w1)
    __shared__ float      scp[2][8][132]; // col partials after xor16 pre-fold

    const int tx = threadIdx.x, ty = threadIdx.y;
    const int tid = ty * 16 + tx;
    const int b = blockIdx.z;
    const int rowBase = blockIdx.y * 128;
    const int colBase = blockIdx.x * COLS_PER_BLOCK;

    // Load this thread's 8 pred points (L2-resident) and pre-pack (negated xyz).
    const float4* pp = g_predP + b * Nn + rowBase + ty * 8;
    ull Px2[8], Py2[8], Pz2[8], Pw2[8];
#pragma unroll
    for (int i = 0; i < 8; i++) {
        float4 P = pp[i];
        Px2[i] = pack2(-P.x, -P.x);
        Py2[i] = pack2(-P.y, -P.y);
        Pz2[i] = pack2(-P.z, -P.z);
        Pw2[i] = pack2( P.w,  P.w);
    }

    float rA[8];
#pragma unroll
    for (int i = 0; i < 8; i++) rA[i] = 3.4e38f;

    const float4* tp = g_tgtP + b * Mm + colBase;

    // Prologue: stage iteration 0 into buffer 0.
    if (tid < 128) {
        float4 T = tp[tid];
        int p = tid >> 1, h = tid & 1;
        float* fxy = (float*)&sTxy[0][p];
        float* fzw = (float*)&sTzw[0][p];
        fxy[h] = T.x; fxy[2 + h] = T.y;
        fzw[h] = T.z; fzw[2 + h] = T.w;
    }
    __syncthreads();

    for (int it = 0; it < COL_ITERS; ++it) {
        const int cur = it & 1;

        // Prefetch next tile into the other buffer (safe: all threads passed the
        // previous sync after finishing reads of that buffer; writers race only
        // with scp-fold readers, which touch different arrays).
        if (it + 1 < COL_ITERS && tid < 128) {
            float4 T = tp[(it + 1) * 128 + tid];
            int p = tid >> 1, h = tid & 1;
            float* fxy = (float*)&sTxy[cur ^ 1][p];
            float* fzw = (float*)&sTzw[cur ^ 1][p];
            fxy[h] = T.x; fxy[2 + h] = T.y;
            fzw[h] = T.z; fzw[2 + h] = T.w;
        }

        float cLo[4], cHi[4];
#pragma unroll
        for (int cm = 0; cm < 4; cm++) {
            const ulonglong2 txy = sTxy[cur][cm * 16 + tx];  // (x0,x1 | y0,y1)
            const ulonglong2 tzw = sTzw[cur][cm * 16 + tx];  // (z0,z1 | w0,w1)
            float cl, ch;
            {
                ull acc = add2(tzw.y, Pw2[0]);
                acc = fma2(Pz2[0], tzw.x, acc);
                acc = fma2(Py2[0], txy.y, acc);
                acc = fma2(Px2[0], txy.x, acc);
                unpack2(acc, cl, ch);
                rA[0] = fminf(rA[0], fminf(cl, ch));
            }
#pragma unroll
            for (int rn = 1; rn < 8; rn++) {
                ull acc = add2(tzw.y, Pw2[rn]);
                acc = fma2(Pz2[rn], tzw.x, acc);
                acc = fma2(Py2[rn], txy.y, acc);
                acc = fma2(Px2[rn], txy.x, acc);
                float lo, hi; unpack2(acc, lo, hi);
                rA[rn] = fminf(rA[rn], fminf(lo, hi));
                cl = fminf(cl, lo);
                ch = fminf(ch, hi);
            }
            // warp pre-fold: (tx,ty) and (tx,ty^1) are lanes xor 16 of one warp
            cLo[cm] = fminf(cl, __shfl_xor_sync(0xffffffffu, cl, 16));
            cHi[cm] = fminf(ch, __shfl_xor_sync(0xffffffffu, ch, 16));
        }

        // Even-ty threads hold the pair-combined partial: store to scp[cur].
        if ((ty & 1) == 0) {
#pragma unroll
            for (int cm = 0; cm < 4; cm++) {
                float2* dst = (float2*)&scp[cur][ty >> 1][cm * 32 + 2 * tx];
                *dst = make_float2(cLo[cm], cHi[cm]);
            }
        }
        __syncthreads();   // scp[cur] ready; next-buffer T staged; reads of sT[cur] done

        if (tid < 128) {
            // balanced tree over 8 partials (independent loads, 3 min levels)
            float v0 = scp[cur][0][tid], v1 = scp[cur][1][tid];
            float v2 = scp[cur][2][tid], v3 = scp[cur][3][tid];
            float v4 = scp[cur][4][tid], v5 = scp[cur][5][tid];
            float v6 = scp[cur][6][tid], v7 = scp[cur][7][tid];
            float m = fminf(fminf(fminf(v0, v1), fminf(v2, v3)),
                            fminf(fminf(v4, v5), fminf(v6, v7)));
            atomicMin(&g_colmin[b * Mm + colBase + it * 128 + tid], f2o(m));
        }
    }

    // Row mins: reduce across the 16 tx lanes (xor 1,2,4,8 stays within ty half)
#pragma unroll
    for (int o = 1; o < 16; o <<= 1) {
#pragma unroll
        for (int rn = 0; rn < 8; rn++)
            rA[rn] = fminf(rA[rn], __shfl_xor_sync(0xffffffffu, rA[rn], o));
    }
    if (tx == 0) {
#pragma unroll
        for (int rn = 0; rn < 8; rn++)
            atomicMin(&g_rowmin[b * Nn + rowBase + ty * 8 + rn], f2o(rA[rn]));
    }
}

// ---------------- edge loss partial sums ----------------
__global__ void edge_kernel(const float* __restrict__ pred, const void* __restrict__ edges) {
    const int b = blockIdx.y;
    const int is64 = g_edges_is64;
    const int*       E32 = (const int*)edges;
    const long long* E64 = (const long long*)edges;
    double s1 = 0.0, s2 = 0.0;
    for (int e = blockIdx.x * blockDim.x + threadIdx.x; e < Ee; e += gridDim.x * blockDim.x) {
        int a, c;
        if (is64) { a = (int)E64[2 * e]; c = (int)E64[2 * e + 1]; }
        else      { a = E32[2 * e];      c = E32[2 * e + 1]; }
        a &= (Nn - 1); c &= (Nn - 1);   // defensive: never OOB even if dtype guess is wrong
        const float* v1 = pred + (size_t)(b * Nn + a) * 3;
        const float* v2 = pred + (size_t)(b * Nn + c) * 3;
        float dx = v1[0] - v2[0], dy = v1[1] - v2[1], dz = v1[2] - v2[2];
        float l = sqrtf(fmaf(dx, dx, fmaf(dy, dy, dz * dz)));
        s1 += (double)l;
        s2 += (double)l * (double)l;
    }
    // warp then block reduce
    for (int o = 16; o > 0; o >>= 1) {
        s1 += __shfl_down_sync(0xffffffffu, s1, o);
        s2 += __shfl_down_sync(0xffffffffu, s2, o);
    }
    __shared__ double sh1[8], sh2[8];
    int lane = threadIdx.x & 31, w = threadIdx.x >> 5;
    if (lane == 0) { sh1[w] = s1; sh2[w] = s2; }
    __syncthreads();
    if (threadIdx.x == 0) {
        double a1 = 0.0, a2 = 0.0;
        for (int k = 0; k < (int)blockDim.x / 32; k++) { a1 += sh1[k]; a2 += sh2[k]; }
        atomicAdd(&g_es1[b], a1);
        atomicAdd(&g_es2[b], a2);
    }
}

// ---------------- grid-wide min-array reduction ----------------
__global__ void reduce_kernel() {
    const int tid = blockIdx.x * blockDim.x + threadIdx.x;
    const int stride = gridDim.x * blockDim.x;
    double sRow = 0.0, sCol = 0.0;
    for (int i = tid; i < Bb * Nn; i += stride) {
        float vr = o2f(g_rowmin[i]);
        float vc = o2f(g_colmin[i]);
        sRow += (double)sqrtf(fmaxf(2.0f * vr, 0.0f));
        sCol += (double)sqrtf(fmaxf(2.0f * vc, 0.0f));
    }
    for (int o = 16; o > 0; o >>= 1) {
        sRow += __shfl_down_sync(0xffffffffu, sRow, o);
        sCol += __shfl_down_sync(0xffffffffu, sCol, o);
    }
    __shared__ double shA[8], shB[8];
    int lane = threadIdx.x & 31, w = threadIdx.x >> 5;
    if (lane == 0) { shA[w] = sRow; shB[w] = sCol; }
    __syncthreads();
    if (threadIdx.x == 0) {
        double a = 0.0, c = 0.0;
#pragma unroll
        for (int k = 0; k < 8; k++) { a += shA[k]; c += shB[k]; }
        atomicAdd(&g_sumRow, a);
        atomicAdd(&g_sumCol, c);
    }
}

// ---------------- final scalar combine ----------------
__global__ void final_kernel(float* __restrict__ out) {
    if (threadIdx.x != 0) return;
    double c_loss = g_sumRow / (double)(Bb * Nn) + g_sumCol / (double)(Bb * Mm);
    double el = 0.0;
    for (int bb = 0; bb < Bb; bb++) {
        double mean = g_es1[bb] / (double)Ee;
        double var = (g_es2[bb] - (double)Ee * mean * mean) / (double)(Ee - 1);
        el += var;
    }
    el /= (double)Bb;
    double total = 1.0 * c_loss + 0.1 * el;
    out[0] = (float)total;
    out[1] = (float)c_loss;
    out[2] = (float)el;
}

// ---------------- launch ----------------
// Order puts pair_kernel at launch #4 (the one ncu captures).
extern "C" void kernel_launch(void* const* d_in, const int* in_sizes, int n_in,
                              void* d_out, int out_size) {
    const float* pred  = (const float*)d_in[0];   // (B,N,3) f32
    const float* tgt   = (const float*)d_in[1];   // (B,M,3) f32
    const void*  edges = d_in[2];                 // (E,2) int32 (JAX x64 off) or int64
    (void)in_sizes; (void)n_in; (void)out_size;

    prep_kernel<<<(Bb * Nn + 255) / 256, 256>>>(pred, tgt, (const int*)edges);
    edge_kernel<<<dim3(192, Bb), 256>>>(pred, edges);
    noop_kernel<<<1, 32>>>();
    pair_kernel<<<dim3(Mm / COLS_PER_BLOCK, Nn / 128, Bb), dim3(16, 16)>>>();
    reduce_kernel<<<128, 256>>>();
    final_kernel<<<1, 32>>>((float*)d_out);
}